// round 17
// baseline (speedup 1.0000x reference)
#include <cuda_runtime.h>
#include <cuda_fp16.h>

#define NU 100000
#define MI 50000
#define NN (NU + MI)
#define D 64
#define ND (NN * D)
#define MAXE 2000000
#define MAXB 16384
#define CHUNK 2048
#define NBLK_I ((MI + CHUNK - 1) / CHUNK)   // 25

// Static scratch (no dynamic allocation allowed).
static __device__ __half g_a[ND];                     // layer 1 out (fp16)
static __device__ __half g_b[ND];                     // layer 2 out (fp16)
static __device__ unsigned long long g_edges[MAXE];   // ITEM half only: {val:f32, col:u32}
static __device__ int g_rowptr[NU + 1];               // user CSR into cols/vals arrays
static __device__ int g_rowptr_i[MI + 1];             // item CSR into g_edges (0-based)
static __device__ int g_cursor[MI];                   // zero at entry; rebuilt+rezeroed
static __device__ int g_blocksum[NBLK_I];             // scan stage-1 block totals
static __device__ int g_degh[512];                    // degree buckets (user 0-255, item 256-511)
static __device__ int g_perm[NN];                     // degree-sorted row order (user | item-local)
static __device__ float g_s[MAXB * D];                // user-node partial accum vectors
static __device__ float g_sreg[MAXB];                 // user-node reg-loss partials

// ---------------------------------------------------------------------------
struct StreamRes {
    cudaStream_t side = nullptr;
    cudaEvent_t eFork = nullptr, ePerm = nullptr, eScat = nullptr, eSide = nullptr;
    bool ok = false;
    StreamRes() {
        if (cudaStreamCreateWithFlags(&side, cudaStreamNonBlocking) != cudaSuccess) return;
        if (cudaEventCreateWithFlags(&eFork, cudaEventDisableTiming) != cudaSuccess) return;
        if (cudaEventCreateWithFlags(&ePerm, cudaEventDisableTiming) != cudaSuccess) return;
        if (cudaEventCreateWithFlags(&eScat, cudaEventDisableTiming) != cudaSuccess) return;
        if (cudaEventCreateWithFlags(&eSide, cudaEventDisableTiming) != cudaSuccess) return;
        ok = true;
    }
};
static StreamRes g_sr;

// ---------------------------------------------------------------------------
// re-zero cursors + degree buckets (tail of launch; entry state is always zero)
__global__ void clear_kernel() {
    int i = blockIdx.x * blockDim.x + threadIdx.x;
    if (i < MI) g_cursor[i] = 0;
    if (i < 512) g_degh[i] = 0;
}

// user rowptr boundary detection (first half, sorted) + item-degree histogram.
// Also zeroes out[2B] (precedes final_join's atomicAdd on the main stream).
__global__ void hist_kernel(const int* __restrict__ rows, int H,
                            float* __restrict__ out, int B) {
    int e = blockIdx.x * blockDim.x + threadIdx.x;
    if (e == 0) out[2 * B] = 0.f;
    if (e >= H) return;
    int cur = __ldg(&rows[e]);
    int prev = (e == 0) ? -1 : __ldg(&rows[e - 1]);
    for (int r = prev + 1; r <= cur; r++) g_rowptr[r] = e;
    if (e == H - 1)
        for (int r = cur + 1; r <= NU; r++) g_rowptr[r] = H;
    atomicAdd(&g_cursor[__ldg(&rows[H + e]) - NU], 1);
}

// Degree-sort P1: bucket histogram (user degrees from rowptr, item from cursor).
__global__ void perm_hist_kernel() {
    int i = blockIdx.x * blockDim.x + threadIdx.x;
    if (i < NU) {
        int d = g_rowptr[i + 1] - g_rowptr[i];
        if (d > 255) d = 255;
        atomicAdd(&g_degh[d], 1);
    } else if (i < NN) {
        int d = g_cursor[i - NU];
        if (d > 255) d = 255;
        atomicAdd(&g_degh[256 + d], 1);
    }
}

// P2: segmented exclusive scan (user buckets 0-255, item buckets 256-511).
__global__ void perm_scan_kernel() {
    __shared__ int sh[512];
    int t = threadIdx.x;
    int c = g_degh[t];
    sh[t] = c;
    __syncthreads();
    for (int off = 1; off < 256; off <<= 1) {
        int y = ((t & 255) >= off) ? sh[t - off] : 0;
        __syncthreads();
        sh[t] += y;
        __syncthreads();
    }
    g_degh[t] = sh[t] - c;   // exclusive prefix within segment
}

// P3: scatter rows into perm by degree bucket.
__global__ void perm_scatter_kernel() {
    int i = blockIdx.x * blockDim.x + threadIdx.x;
    if (i < NU) {
        int d = g_rowptr[i + 1] - g_rowptr[i];
        if (d > 255) d = 255;
        int pos = atomicAdd(&g_degh[d], 1);
        g_perm[pos] = i;
    } else if (i < NN) {
        int d = g_cursor[i - NU];
        if (d > 255) d = 255;
        int pos = atomicAdd(&g_degh[256 + d], 1);
        g_perm[NU + pos] = i - NU;   // item-local index
    }
}

// multi-block item scan, stage 1: per-chunk exclusive scan + block totals.
__global__ void scan1_kernel() {
    __shared__ int ssum[256];
    int b = blockIdx.x, t = threadIdx.x;
    int base = b * CHUNK + t * 8;
    int v[8];
    int s = 0;
#pragma unroll
    for (int k = 0; k < 8; k++) {
        int idx = base + k;
        int c = (idx < MI) ? g_cursor[idx] : 0;
        v[k] = s;
        s += c;
    }
    int s_orig = s;
    ssum[t] = s;
    __syncthreads();
    for (int off = 1; off < 256; off <<= 1) {
        int y = (t >= off) ? ssum[t - off] : 0;
        __syncthreads();
        ssum[t] += y;
        __syncthreads();
    }
    int excl = ssum[t] - s_orig;
#pragma unroll
    for (int k = 0; k < 8; k++) {
        int idx = base + k;
        if (idx < MI) g_rowptr_i[idx] = excl + v[k];
    }
    if (t == 255) g_blocksum[b] = ssum[255];
}

// stage 2: add per-block prefix; initialize cursors; cap rowptr.
__global__ void scan2_kernel(int H) {
    int b = blockIdx.x, t = threadIdx.x;
    int off = 0;
    for (int k = 0; k < b; k++) off += g_blocksum[k];
    int base = b * CHUNK + t * 8;
#pragma unroll
    for (int k = 0; k < 8; k++) {
        int idx = base + k;
        if (idx < MI) {
            int r = g_rowptr_i[idx] + off;
            g_rowptr_i[idx] = r;
            g_cursor[idx] = r;
        }
    }
    if (b == 0 && t == 0) g_rowptr_i[MI] = H;
}

// scatter second-half edges into item CSR (0-based positions in g_edges).
__global__ void scatter_edges_kernel(const int* __restrict__ rows,
                                     const int* __restrict__ cols,
                                     const float* __restrict__ vals, int H) {
    int t = blockIdx.x * blockDim.x + threadIdx.x;
    if (t >= H) return;
    int e = H + t;
    int r = __ldg(&rows[e]) - NU;
    int pos = atomicAdd(&g_cursor[r], 1);
    unsigned long long pk =
        ((unsigned long long)__float_as_uint(__ldg(&vals[e])) << 32) |
        (unsigned int)__ldg(&cols[e]);
    g_edges[pos] = pk;
}

// ---------------------------------------------------------------------------
// LAYER-1 SpMM (fp32 gather, 16 lanes/row), rows scheduled via degree-sorted
// perm so the 2 rows sharing a warp have (near-)equal trip counts.
// RAW=true: user rows (gather ei0, col-NU). RAW=false: item rows (gather eu0).
template <bool RAW>
__global__ void spmm_l1_kernel(const float* __restrict__ srcTab,
                               __half* __restrict__ dst,
                               int cnt, int permBase,
                               const int* __restrict__ cols,
                               const float* __restrict__ vals) {
    int gid = blockIdx.x * blockDim.x + threadIdx.x;
    int idx = gid >> 4;
    int l = gid & 15;
    if (idx >= cnt) return;
    int r = __ldg(&g_perm[permBase + idx]);   // user node id / item-local id
    int beg, end, drow;
    if (RAW) { beg = g_rowptr[r];   end = g_rowptr[r + 1];   drow = r; }
    else     { beg = g_rowptr_i[r]; end = g_rowptr_i[r + 1]; drow = NU + r; }
    const float4* sp = (const float4*)srcTab;   // 16 x float4 per row

    float4 a = make_float4(0.f, 0.f, 0.f, 0.f);
    int j = beg;
    for (; j + 4 <= end; j += 4) {
        int c0, c1, c2, c3;
        float v0, v1, v2, v3;
        if (RAW) {
            c0 = __ldg(&cols[j])     - NU; v0 = __ldg(&vals[j]);
            c1 = __ldg(&cols[j + 1]) - NU; v1 = __ldg(&vals[j + 1]);
            c2 = __ldg(&cols[j + 2]) - NU; v2 = __ldg(&vals[j + 2]);
            c3 = __ldg(&cols[j + 3]) - NU; v3 = __ldg(&vals[j + 3]);
        } else {
            unsigned long long pk0 = __ldg(&g_edges[j]);
            unsigned long long pk1 = __ldg(&g_edges[j + 1]);
            unsigned long long pk2 = __ldg(&g_edges[j + 2]);
            unsigned long long pk3 = __ldg(&g_edges[j + 3]);
            c0 = (int)(unsigned int)pk0; v0 = __uint_as_float((unsigned int)(pk0 >> 32));
            c1 = (int)(unsigned int)pk1; v1 = __uint_as_float((unsigned int)(pk1 >> 32));
            c2 = (int)(unsigned int)pk2; v2 = __uint_as_float((unsigned int)(pk2 >> 32));
            c3 = (int)(unsigned int)pk3; v3 = __uint_as_float((unsigned int)(pk3 >> 32));
        }
        float4 x0 = __ldg(sp + c0 * 16 + l);
        float4 x1 = __ldg(sp + c1 * 16 + l);
        float4 x2 = __ldg(sp + c2 * 16 + l);
        float4 x3 = __ldg(sp + c3 * 16 + l);
        a.x += v0 * x0.x; a.y += v0 * x0.y; a.z += v0 * x0.z; a.w += v0 * x0.w;
        a.x += v1 * x1.x; a.y += v1 * x1.y; a.z += v1 * x1.z; a.w += v1 * x1.w;
        a.x += v2 * x2.x; a.y += v2 * x2.y; a.z += v2 * x2.z; a.w += v2 * x2.w;
        a.x += v3 * x3.x; a.y += v3 * x3.y; a.z += v3 * x3.z; a.w += v3 * x3.w;
    }
    for (; j < end; j++) {
        int c; float v;
        if (RAW) { c = __ldg(&cols[j]) - NU; v = __ldg(&vals[j]); }
        else {
            unsigned long long pk = __ldg(&g_edges[j]);
            c = (int)(unsigned int)pk; v = __uint_as_float((unsigned int)(pk >> 32));
        }
        float4 x = __ldg(sp + c * 16 + l);
        a.x += v * x.x; a.y += v * x.y; a.z += v * x.z; a.w += v * x.w;
    }

    half2 o[2];
    o[0] = __floats2half2_rn(a.x, a.y);
    o[1] = __floats2half2_rn(a.z, a.w);
    ((uint2*)dst)[drow * 16 + l] = *(uint2*)o;
}

// LAYER-2 SpMM (fp16 g_a gather, 8 lanes/row), degree-sorted rows.
template <bool RAW>
__global__ void spmm_l2_kernel(const __half* __restrict__ src,
                               __half* __restrict__ dst,
                               int cnt, int permBase,
                               const int* __restrict__ cols,
                               const float* __restrict__ vals) {
    int gid = blockIdx.x * blockDim.x + threadIdx.x;
    int idx = gid >> 3;
    int l = gid & 7;
    if (idx >= cnt) return;
    int r = __ldg(&g_perm[permBase + idx]);
    int beg, end, drow;
    if (RAW) { beg = g_rowptr[r];   end = g_rowptr[r + 1];   drow = r; }
    else     { beg = g_rowptr_i[r]; end = g_rowptr_i[r + 1]; drow = NU + r; }
    const uint4* sp = (const uint4*)src;

    float s0 = 0.f, s1 = 0.f, s2 = 0.f, s3 = 0.f,
          s4 = 0.f, s5 = 0.f, s6 = 0.f, s7 = 0.f;

#define ACCV(V, X) {                                                     \
        half2* h = (half2*)&(X);                                         \
        float2 f0 = __half22float2(h[0]);                                \
        float2 f1 = __half22float2(h[1]);                                \
        float2 f2 = __half22float2(h[2]);                                \
        float2 f3 = __half22float2(h[3]);                                \
        s0 += (V) * f0.x; s1 += (V) * f0.y; s2 += (V) * f1.x; s3 += (V) * f1.y; \
        s4 += (V) * f2.x; s5 += (V) * f2.y; s6 += (V) * f3.x; s7 += (V) * f3.y; }

    int j = beg;
    for (; j + 4 <= end; j += 4) {
        int c0, c1, c2, c3;
        float v0, v1, v2, v3;
        if (RAW) {
            c0 = __ldg(&cols[j]);     v0 = __ldg(&vals[j]);
            c1 = __ldg(&cols[j + 1]); v1 = __ldg(&vals[j + 1]);
            c2 = __ldg(&cols[j + 2]); v2 = __ldg(&vals[j + 2]);
            c3 = __ldg(&cols[j + 3]); v3 = __ldg(&vals[j + 3]);
        } else {
            unsigned long long pk0 = __ldg(&g_edges[j]);
            unsigned long long pk1 = __ldg(&g_edges[j + 1]);
            unsigned long long pk2 = __ldg(&g_edges[j + 2]);
            unsigned long long pk3 = __ldg(&g_edges[j + 3]);
            c0 = (int)(unsigned int)pk0; v0 = __uint_as_float((unsigned int)(pk0 >> 32));
            c1 = (int)(unsigned int)pk1; v1 = __uint_as_float((unsigned int)(pk1 >> 32));
            c2 = (int)(unsigned int)pk2; v2 = __uint_as_float((unsigned int)(pk2 >> 32));
            c3 = (int)(unsigned int)pk3; v3 = __uint_as_float((unsigned int)(pk3 >> 32));
        }
        uint4 x0 = __ldg(sp + c0 * 8 + l);
        uint4 x1 = __ldg(sp + c1 * 8 + l);
        uint4 x2 = __ldg(sp + c2 * 8 + l);
        uint4 x3 = __ldg(sp + c3 * 8 + l);
        ACCV(v0, x0) ACCV(v1, x1) ACCV(v2, x2) ACCV(v3, x3)
    }
    for (; j < end; j++) {
        int c; float v;
        if (RAW) { c = __ldg(&cols[j]); v = __ldg(&vals[j]); }
        else {
            unsigned long long pk = __ldg(&g_edges[j]);
            c = (int)(unsigned int)pk; v = __uint_as_float((unsigned int)(pk >> 32));
        }
        uint4 x = __ldg(sp + c * 8 + l);
        ACCV(v, x)
    }
#undef ACCV

    half2 o[4];
    o[0] = __floats2half2_rn(s0, s1);
    o[1] = __floats2half2_rn(s2, s3);
    o[2] = __floats2half2_rn(s4, s5);
    o[3] = __floats2half2_rn(s6, s7);
    ((uint4*)dst)[drow * 8 + l] = *(uint4*)o;
}

// ---------------------------------------------------------------------------
// l3 gathers over g_b (fp16 half2 per lane).
__device__ __forceinline__ void l3_gather_pk(int beg, int end, int lane,
                                             float& ax, float& ay) {
    const unsigned* sp = (const unsigned*)g_b;
    int j = beg;
    for (; j + 4 <= end; j += 4) {
        unsigned long long pk0 = __ldg(&g_edges[j]);
        unsigned long long pk1 = __ldg(&g_edges[j + 1]);
        unsigned long long pk2 = __ldg(&g_edges[j + 2]);
        unsigned long long pk3 = __ldg(&g_edges[j + 3]);
        unsigned x0 = __ldg(sp + (int)(unsigned int)pk0 * 32 + lane);
        unsigned x1 = __ldg(sp + (int)(unsigned int)pk1 * 32 + lane);
        unsigned x2 = __ldg(sp + (int)(unsigned int)pk2 * 32 + lane);
        unsigned x3 = __ldg(sp + (int)(unsigned int)pk3 * 32 + lane);
        float v0 = __uint_as_float((unsigned int)(pk0 >> 32));
        float v1 = __uint_as_float((unsigned int)(pk1 >> 32));
        float v2 = __uint_as_float((unsigned int)(pk2 >> 32));
        float v3 = __uint_as_float((unsigned int)(pk3 >> 32));
        float2 f0 = __half22float2(*(half2*)&x0);
        float2 f1 = __half22float2(*(half2*)&x1);
        float2 f2 = __half22float2(*(half2*)&x2);
        float2 f3 = __half22float2(*(half2*)&x3);
        ax += v0 * f0.x; ay += v0 * f0.y;
        ax += v1 * f1.x; ay += v1 * f1.y;
        ax += v2 * f2.x; ay += v2 * f2.y;
        ax += v3 * f3.x; ay += v3 * f3.y;
    }
    for (; j < end; j++) {
        unsigned long long pk = __ldg(&g_edges[j]);
        unsigned x = __ldg(sp + (int)(unsigned int)pk * 32 + lane);
        float v = __uint_as_float((unsigned int)(pk >> 32));
        float2 f = __half22float2(*(half2*)&x);
        ax += v * f.x; ay += v * f.y;
    }
}

__device__ __forceinline__ void l3_gather_raw(int beg, int end, int lane,
                                              const int* __restrict__ cols,
                                              const float* __restrict__ vals,
                                              float& ax, float& ay) {
    const unsigned* sp = (const unsigned*)g_b;
    int j = beg;
    for (; j + 4 <= end; j += 4) {
        int c0 = __ldg(&cols[j]);     float v0 = __ldg(&vals[j]);
        int c1 = __ldg(&cols[j + 1]); float v1 = __ldg(&vals[j + 1]);
        int c2 = __ldg(&cols[j + 2]); float v2 = __ldg(&vals[j + 2]);
        int c3 = __ldg(&cols[j + 3]); float v3 = __ldg(&vals[j + 3]);
        unsigned x0 = __ldg(sp + c0 * 32 + lane);
        unsigned x1 = __ldg(sp + c1 * 32 + lane);
        unsigned x2 = __ldg(sp + c2 * 32 + lane);
        unsigned x3 = __ldg(sp + c3 * 32 + lane);
        float2 f0 = __half22float2(*(half2*)&x0);
        float2 f1 = __half22float2(*(half2*)&x1);
        float2 f2 = __half22float2(*(half2*)&x2);
        float2 f3 = __half22float2(*(half2*)&x3);
        ax += v0 * f0.x; ay += v0 * f0.y;
        ax += v1 * f1.x; ay += v1 * f1.y;
        ax += v2 * f2.x; ay += v2 * f2.y;
        ax += v3 * f3.x; ay += v3 * f3.y;
    }
    for (; j < end; j++) {
        int c = __ldg(&cols[j]); float v = __ldg(&vals[j]);
        unsigned x = __ldg(sp + c * 32 + lane);
        float2 f = __half22float2(*(half2*)&x);
        ax += v * f.x; ay += v * f.y;
    }
}

// USER-node partial (SIDE stream, overlapped with main's L2_user):
// au_partial = e0[u] + l1[u] + l3(u over g_b item cols); g_b[u] added in join.
__global__ void final_user_partial(const float* __restrict__ eu0,
                                   const int* __restrict__ cols,
                                   const float* __restrict__ vals,
                                   const int* __restrict__ user, int B) {
    int w = (int)((blockIdx.x * (long long)blockDim.x + threadIdx.x) >> 5);
    int lane = threadIdx.x & 31;
    if (w >= B) return;
    int u = __ldg(&user[w]);
    float2 v0 = __ldg((const float2*)eu0 + u * 32 + lane);
    float ax = v0.x, ay = v0.y;
    float sq = v0.x * v0.x + v0.y * v0.y;
    float2 t = __half22float2(((const half2*)g_a)[u * 32 + lane]);
    ax += t.x; ay += t.y;
    l3_gather_raw(g_rowptr[u], g_rowptr[u + 1], lane, cols, vals, ax, ay);
    g_s[w * D + 2 * lane] = ax;
    g_s[w * D + 2 * lane + 1] = ay;
#pragma unroll
    for (int o = 16; o; o >>= 1) sq += __shfl_xor_sync(0xFFFFFFFFu, sq, o);
    if (lane == 0) g_sreg[w] = sq;
}

// JOIN (main, after everything): item-node accums + add g_b[u] + dots.
__global__ void final_join(const float* __restrict__ ei0,
                           const int* __restrict__ user,
                           const int* __restrict__ item_i,
                           const int* __restrict__ item_j,
                           float* __restrict__ out, int B) {
    __shared__ float sm[3][64];
    __shared__ float regp[2];
    int bidx = blockIdx.x;
    int w = threadIdx.x >> 5;
    int lane = threadIdx.x & 31;
    if (bidx >= B) return;

    if (w == 0) {
        int u = __ldg(&user[bidx]);
        float ax = g_s[bidx * D + 2 * lane];
        float ay = g_s[bidx * D + 2 * lane + 1];
        float2 t = __half22float2(((const half2*)g_b)[u * 32 + lane]);
        ax += t.x; ay += t.y;
        sm[0][2 * lane] = ax;
        sm[0][2 * lane + 1] = ay;
    } else {
        int it = (w == 1) ? __ldg(&item_i[bidx]) : __ldg(&item_j[bidx]);
        int n = NU + it;
        float2 v0 = __ldg((const float2*)ei0 + it * 32 + lane);
        float ax = v0.x, ay = v0.y;
        float sq = v0.x * v0.x + v0.y * v0.y;
        float2 t;
        t = __half22float2(((const half2*)g_a)[n * 32 + lane]); ax += t.x; ay += t.y;
        t = __half22float2(((const half2*)g_b)[n * 32 + lane]); ax += t.x; ay += t.y;
        l3_gather_pk(g_rowptr_i[it], g_rowptr_i[it + 1], lane, ax, ay);
        sm[w][2 * lane] = ax;
        sm[w][2 * lane + 1] = ay;
#pragma unroll
        for (int o = 16; o; o >>= 1) sq += __shfl_xor_sync(0xFFFFFFFFu, sq, o);
        if (lane == 0) regp[w - 1] = sq;
    }
    __syncthreads();

    if (w == 0) {
        float p = sm[0][2 * lane] * sm[1][2 * lane]
                + sm[0][2 * lane + 1] * sm[1][2 * lane + 1];
#pragma unroll
        for (int o = 16; o; o >>= 1) p += __shfl_xor_sync(0xFFFFFFFFu, p, o);
        if (lane == 0) out[bidx] = p * (1.f / 16.f);
    } else if (w == 1) {
        float p = sm[0][2 * lane] * sm[2][2 * lane]
                + sm[0][2 * lane + 1] * sm[2][2 * lane + 1];
#pragma unroll
        for (int o = 16; o; o >>= 1) p += __shfl_xor_sync(0xFFFFFFFFu, p, o);
        if (lane == 0) out[B + bidx] = p * (1.f / 16.f);
    } else {
        if (lane == 0) {
            float reg = g_sreg[bidx] + regp[0] + regp[1];
            atomicAdd(out + 2 * B, reg * (0.5f / (float)B));
        }
    }
}

// ---------------------------------------------------------------------------
extern "C" void kernel_launch(void* const* d_in, const int* in_sizes, int n_in,
                              void* d_out, int out_size) {
    const float* eu0    = (const float*)d_in[0];
    const float* ei0    = (const float*)d_in[1];
    const int*   rows   = (const int*)d_in[2];
    const int*   cols   = (const int*)d_in[3];
    const float* vals   = (const float*)d_in[4];
    const int*   user   = (const int*)d_in[5];
    const int*   item_i = (const int*)d_in[6];
    const int*   item_j = (const int*)d_in[7];

    int E = in_sizes[2];
    int H = E / 2;          // first half: user rows (sorted); second: item rows
    int B = in_sizes[5];
    float* out = (float*)d_out;

    __half *pa, *pb;
    cudaGetSymbolAddress((void**)&pa, g_a);
    cudaGetSymbolAddress((void**)&pb, g_b);

    const int T = 256;
    int u1grid = (NU * 16 + T - 1) / T;
    int i1grid = (MI * 16 + T - 1) / T;
    int u2grid = (NU * 8 + T - 1) / T;
    int i2grid = (MI * 8 + T - 1) / T;
    int ngrid  = (NN + T - 1) / T;
    int cgrid  = (MI + T - 1) / T;
    int pgrid  = (B * 32 + T - 1) / T;

    if (g_sr.ok) {
        cudaStream_t s = g_sr.side;
        cudaEventRecord(g_sr.eFork, 0);
        cudaStreamWaitEvent(s, g_sr.eFork, 0);

        // main: hist -> degree-sort perm -> item CSR chain
        hist_kernel<<<(H + T - 1) / T, T>>>(rows, H, out, B);
        perm_hist_kernel<<<ngrid, T>>>();
        perm_scan_kernel<<<1, 512>>>();
        perm_scatter_kernel<<<ngrid, T>>>();
        cudaEventRecord(g_sr.ePerm, 0);
        scan1_kernel<<<NBLK_I, 256>>>();
        scan2_kernel<<<NBLK_I, 256>>>(H);
        scatter_edges_kernel<<<(H + T - 1) / T, T>>>(rows, cols, vals, H);
        cudaEventRecord(g_sr.eScat, 0);

        // side: L1 user rows (needs user rowptr + perm [ePerm])
        cudaStreamWaitEvent(s, g_sr.ePerm, 0);
        spmm_l1_kernel<true><<<u1grid, T, 0, s>>>(ei0, pa, NU, 0, cols, vals);
        // side: L2 item rows (g_a user cols same-stream; item CSR [eScat])
        cudaStreamWaitEvent(s, g_sr.eScat, 0);
        spmm_l2_kernel<false><<<i2grid, T, 0, s>>>(pa, pb, MI, NU, cols, vals);
        // side: user-node final partial (L1_user + L2_item same-stream)
        final_user_partial<<<pgrid, T, 0, s>>>(eu0, cols, vals, user, B);
        // side: tail clear (cursors/degh; all uses complete at this point)
        clear_kernel<<<cgrid, T, 0, s>>>();
        cudaEventRecord(g_sr.eSide, s);

        // main: L1 item rows (scatter + perm same-stream)
        spmm_l1_kernel<false><<<i1grid, T>>>(eu0, pa, MI, NU, cols, vals);
        // main: L2 user rows (g_a item cols = L1_item same-stream)
        spmm_l2_kernel<true><<<u2grid, T>>>(pa, pb, NU, 0, cols, vals);

        // join side, then item-node accums + dots
        cudaStreamWaitEvent(0, g_sr.eSide, 0);
        final_join<<<B, 96>>>(ei0, user, item_i, item_j, out, B);
    } else {
        // serial fallback (single stream)
        hist_kernel<<<(H + T - 1) / T, T>>>(rows, H, out, B);
        perm_hist_kernel<<<ngrid, T>>>();
        perm_scan_kernel<<<1, 512>>>();
        perm_scatter_kernel<<<ngrid, T>>>();
        scan1_kernel<<<NBLK_I, 256>>>();
        scan2_kernel<<<NBLK_I, 256>>>(H);
        scatter_edges_kernel<<<(H + T - 1) / T, T>>>(rows, cols, vals, H);
        spmm_l1_kernel<true ><<<u1grid, T>>>(ei0, pa, NU, 0, cols, vals);
        spmm_l1_kernel<false><<<i1grid, T>>>(eu0, pa, MI, NU, cols, vals);
        spmm_l2_kernel<false><<<i2grid, T>>>(pa, pb, MI, NU, cols, vals);
        spmm_l2_kernel<true ><<<u2grid, T>>>(pa, pb, NU, 0, cols, vals);
        final_user_partial<<<pgrid, T>>>(eu0, cols, vals, user, B);
        clear_kernel<<<cgrid, T>>>();
        final_join<<<B, 96>>>(ei0, user, item_i, item_j, out, B);
    }
}